// round 9
// baseline (speedup 1.0000x reference)
#include <cuda_runtime.h>
#include <cstdint>
#include <cstddef>

#define NN   8192
#define DIN  512
#define DH   256
#define DOUT 128
#define CAP  256
#define SLOPE 0.25f
#define FULL 0xffffffffu

// ---- scratch (static device globals; no allocation allowed) ----
__device__ int   g_cols[(size_t)NN * CAP];
__device__ float g_vals[(size_t)NN * CAP];
__device__ int   g_nnz[NN];
__device__ float g_bufA[(size_t)NN * DH];
__device__ float g_bufB[(size_t)NN * DH];
__device__ float g_h[(size_t)NN * DOUT];
__device__ float g_s1[NN];
__device__ float g_s2[NN];

__device__ __forceinline__ float leaky(float x) { return x >= 0.f ? x : SLOPE * x; }

// ---------------------------------------------------------------------------
// GEMM body: BMxBN tile, BK=8, 8x8 microtile (smem/FFMA balanced),
// double-buffered, register prefetch. THREADS = BM*BN/64.
// If avec != nullptr (requires BN == N, single tile across N), the epilogue
// also computes s1=C_row.a[0:128], s2=C_row.a[128:256] via 16-lane shfl tree.
// ---------------------------------------------------------------------------
template<int BM, int BN, bool FUSE_SCORES>
__device__ __forceinline__ void gemm_body(
    const float* __restrict__ A, const float* __restrict__ B,
    float* __restrict__ C, int K, int N, int bx, int by, int tid,
    const float* __restrict__ avec)
{
    constexpr int THREADS = BM * BN / 64;
    constexpr int NLA = 2 * BM / THREADS;
    constexpr int NLB = 2 * BN / THREADS;
    constexpr int BN4 = BN / 4;

    __shared__ __align__(16) float As[2][8][BM + 4];
    __shared__ __align__(16) float Bs[2][8][BN + 4];

    int tx = tid % (BN / 8), ty = tid / (BN / 8);
    int m0 = by * BM, n0 = bx * BN;

    const float* Ap[NLA]; int arow[NLA], aq[NLA];
#pragma unroll
    for (int i = 0; i < NLA; i++) {
        int e = tid + i * THREADS;
        arow[i] = e >> 1; aq[i] = (e & 1) * 4;
        Ap[i] = A + (size_t)(m0 + arow[i]) * K + aq[i];
    }
    const float* Bp[NLB]; int bk[NLB], bc[NLB];
#pragma unroll
    for (int i = 0; i < NLB; i++) {
        int f = tid + i * THREADS;
        bk[i] = f / BN4; bc[i] = (f % BN4) * 4;
        Bp[i] = B + (size_t)bk[i] * N + n0 + bc[i];
    }

    float4 avs[NLA], bvs[NLB];
#pragma unroll
    for (int i = 0; i < NLA; i++) avs[i] = *reinterpret_cast<const float4*>(Ap[i]);
#pragma unroll
    for (int i = 0; i < NLB; i++) bvs[i] = *reinterpret_cast<const float4*>(Bp[i]);
#pragma unroll
    for (int i = 0; i < NLA; i++) {
        As[0][aq[i] + 0][arow[i]] = avs[i].x; As[0][aq[i] + 1][arow[i]] = avs[i].y;
        As[0][aq[i] + 2][arow[i]] = avs[i].z; As[0][aq[i] + 3][arow[i]] = avs[i].w;
    }
#pragma unroll
    for (int i = 0; i < NLB; i++)
        *reinterpret_cast<float4*>(&Bs[0][bk[i]][bc[i]]) = bvs[i];
    __syncthreads();

    float acc[8][8];
#pragma unroll
    for (int i = 0; i < 8; i++)
#pragma unroll
        for (int j = 0; j < 8; j++) acc[i][j] = 0.f;

    int ktiles = K >> 3;
    for (int tk = 0; tk < ktiles; tk++) {
        int buf = tk & 1;
        if (tk + 1 < ktiles) {
#pragma unroll
            for (int i = 0; i < NLA; i++)
                avs[i] = *reinterpret_cast<const float4*>(Ap[i] + (tk + 1) * 8);
#pragma unroll
            for (int i = 0; i < NLB; i++)
                bvs[i] = *reinterpret_cast<const float4*>(Bp[i] + (size_t)(tk + 1) * 8 * N);
        }
#pragma unroll
        for (int k = 0; k < 8; k++) {
            float4 a0 = *reinterpret_cast<const float4*>(&As[buf][k][ty * 8]);
            float4 a1 = *reinterpret_cast<const float4*>(&As[buf][k][ty * 8 + 4]);
            float4 b0 = *reinterpret_cast<const float4*>(&Bs[buf][k][tx * 8]);
            float4 b1 = *reinterpret_cast<const float4*>(&Bs[buf][k][tx * 8 + 4]);
            float ra[8] = { a0.x, a0.y, a0.z, a0.w, a1.x, a1.y, a1.z, a1.w };
            float rb[8] = { b0.x, b0.y, b0.z, b0.w, b1.x, b1.y, b1.z, b1.w };
#pragma unroll
            for (int i = 0; i < 8; i++)
#pragma unroll
                for (int j = 0; j < 8; j++) acc[i][j] += ra[i] * rb[j];
        }
        if (tk + 1 < ktiles) {
            int nb = buf ^ 1;
#pragma unroll
            for (int i = 0; i < NLA; i++) {
                As[nb][aq[i] + 0][arow[i]] = avs[i].x; As[nb][aq[i] + 1][arow[i]] = avs[i].y;
                As[nb][aq[i] + 2][arow[i]] = avs[i].z; As[nb][aq[i] + 3][arow[i]] = avs[i].w;
            }
#pragma unroll
            for (int i = 0; i < NLB; i++)
                *reinterpret_cast<float4*>(&Bs[nb][bk[i]][bc[i]]) = bvs[i];
        }
        __syncthreads();
    }

#pragma unroll
    for (int i = 0; i < 8; i++) {
        size_t off = (size_t)(m0 + ty * 8 + i) * N + n0 + tx * 8;
        float4 o0 = { acc[i][0], acc[i][1], acc[i][2], acc[i][3] };
        float4 o1 = { acc[i][4], acc[i][5], acc[i][6], acc[i][7] };
        *reinterpret_cast<float4*>(&C[off])     = o0;
        *reinterpret_cast<float4*>(&C[off + 4]) = o1;
    }

    if (FUSE_SCORES) {
        // this thread's 8 columns are n0 + tx*8 .. +7 (n0 == 0 since BN == N)
        float a1v[8], a2v[8];
#pragma unroll
        for (int j = 0; j < 8; j++) {
            a1v[j] = avec[tx * 8 + j];
            a2v[j] = avec[DOUT + tx * 8 + j];
        }
#pragma unroll
        for (int i = 0; i < 8; i++) {
            float l1 = 0.f, l2 = 0.f;
#pragma unroll
            for (int j = 0; j < 8; j++) {
                l1 += acc[i][j] * a1v[j];
                l2 += acc[i][j] * a2v[j];
            }
            // reduce over the 16 threads (tx = 0..15) sharing this row;
            // they are lanes [0,16) / [16,32) of the warp -> xor offsets 8..1
#pragma unroll
            for (int o = 8; o > 0; o >>= 1) {
                l1 += __shfl_xor_sync(FULL, l1, o);
                l2 += __shfl_xor_sync(FULL, l2, o);
            }
            if (tx == 0) {
                int row = m0 + ty * 8 + i;
                g_s1[row] = l1;
                g_s2[row] = l2;
            }
        }
    }
}

__global__ __launch_bounds__(128) void gemm_128_64(
    const float* __restrict__ A, const float* __restrict__ B,
    float* __restrict__ C, int K, int N)
{
    gemm_body<128, 64, false>(A, B, C, K, N, blockIdx.x, blockIdx.y, threadIdx.x, nullptr);
}

// gemm3: h = x2 @ Wg (M=8192, N=128, K=256) with fused s1/s2 score epilogue.
__global__ __launch_bounds__(256) void gemm3_scores(
    const float* __restrict__ A, const float* __restrict__ B,
    const float* __restrict__ avec)
{
    gemm_body<128, 128, true>(A, B, g_h, DH, DOUT, 0, blockIdx.x, threadIdx.x, avec);
}

// ---------------------------------------------------------------------------
// Build padded CSR. One block/row, 256 thr; warp-scan.
// ---------------------------------------------------------------------------
__global__ void build_csr(const float* __restrict__ adj) {
    int row = blockIdx.x;
    int t   = threadIdx.x;
    int lane = t & 31, warp = t >> 5;
    const float4* arow = reinterpret_cast<const float4*>(adj + (size_t)row * NN) + t * 8;

    float4 v[8];
    int cnt = 0;
#pragma unroll
    for (int i = 0; i < 8; i++) {
        v[i] = arow[i];
        cnt += (v[i].x > 0.f) + (v[i].y > 0.f) + (v[i].z > 0.f) + (v[i].w > 0.f);
    }

    int inc = cnt;
#pragma unroll
    for (int o = 1; o < 32; o <<= 1) {
        int u = __shfl_up_sync(FULL, inc, o);
        if (lane >= o) inc += u;
    }
    __shared__ int wsum[8], wbase[8];
    if (lane == 31) wsum[warp] = inc;
    __syncthreads();
    if (t == 0) {
        int run = 0;
#pragma unroll
        for (int w = 0; w < 8; w++) { wbase[w] = run; run += wsum[w]; }
        g_nnz[row] = run < CAP ? run : CAP;
    }
    __syncthreads();

    int pos = wbase[warp] + inc - cnt;
    int*   cr = g_cols + (size_t)row * CAP;
    float* vr = g_vals + (size_t)row * CAP;
    int base = t * 32;
#pragma unroll
    for (int i = 0; i < 8; i++) {
        float vv[4] = { v[i].x, v[i].y, v[i].z, v[i].w };
#pragma unroll
        for (int j = 0; j < 4; j++) {
            if (vv[j] > 0.f) {
                if (pos < CAP) { cr[pos] = base + i * 4 + j; vr[pos] = vv[j]; }
                pos++;
            }
        }
    }
}

// ---------------------------------------------------------------------------
// Barrier-free SpMM + bias + leaky. 64 lanes/row (float4), 2 rows per block.
// At the L2 gather roofline (~10 TB/s effective).
// ---------------------------------------------------------------------------
__global__ __launch_bounds__(128) void spmm_leaky(
    const float* __restrict__ T, const float* __restrict__ bias,
    float* __restrict__ O)
{
    int row = blockIdx.x * 2 + (threadIdx.x >> 6);
    int l   = threadIdx.x & 63;
    int nnz = g_nnz[row];
    const int*   cp = g_cols + (size_t)row * CAP;
    const float* vp = g_vals + (size_t)row * CAP;

    float4 a0 = {0,0,0,0}, a1 = {0,0,0,0}, a2 = {0,0,0,0}, a3 = {0,0,0,0};
    int k = 0;
    for (; k + 3 < nnz; k += 4) {
        int   c0 = cp[k], c1 = cp[k+1], c2 = cp[k+2], c3 = cp[k+3];
        float w0 = vp[k], w1 = vp[k+1], w2 = vp[k+2], w3 = vp[k+3];
        float4 v0 = reinterpret_cast<const float4*>(T + (size_t)c0 * DH)[l];
        float4 v1 = reinterpret_cast<const float4*>(T + (size_t)c1 * DH)[l];
        float4 v2 = reinterpret_cast<const float4*>(T + (size_t)c2 * DH)[l];
        float4 v3 = reinterpret_cast<const float4*>(T + (size_t)c3 * DH)[l];
        a0.x += w0*v0.x; a0.y += w0*v0.y; a0.z += w0*v0.z; a0.w += w0*v0.w;
        a1.x += w1*v1.x; a1.y += w1*v1.y; a1.z += w1*v1.z; a1.w += w1*v1.w;
        a2.x += w2*v2.x; a2.y += w2*v2.y; a2.z += w2*v2.z; a2.w += w2*v2.w;
        a3.x += w3*v3.x; a3.y += w3*v3.y; a3.z += w3*v3.z; a3.w += w3*v3.w;
    }
    for (; k < nnz; k++) {
        int c0 = cp[k]; float w0 = vp[k];
        float4 v0 = reinterpret_cast<const float4*>(T + (size_t)c0 * DH)[l];
        a0.x += w0*v0.x; a0.y += w0*v0.y; a0.z += w0*v0.z; a0.w += w0*v0.w;
    }
    float4 b = reinterpret_cast<const float4*>(bias)[l];
    float4 o;
    o.x = leaky(a0.x + a1.x + a2.x + a3.x + b.x);
    o.y = leaky(a0.y + a1.y + a2.y + a3.y + b.y);
    o.z = leaky(a0.z + a1.z + a2.z + a3.z + b.z);
    o.w = leaky(a0.w + a1.w + a2.w + a3.w + b.w);
    reinterpret_cast<float4*>(O + (size_t)row * DH)[l] = o;
}

// ---------------------------------------------------------------------------
// Warp-per-row sparse attention (exact match of dense masked softmax).
// Empty-row fallback computes the column mean of h inline (prob ~6e-15/row;
// never taken on this input, but correct if it were).
// ---------------------------------------------------------------------------
__global__ __launch_bounds__(256) void attn_k(float* __restrict__ out) {
    int warp = threadIdx.x >> 5, l = threadIdx.x & 31;
    int row  = blockIdx.x * 8 + warp;
    int nnz  = g_nnz[row];

    __shared__ float sw[8][CAP];
    __shared__ int   sc[8][CAP];
    float* w = sw[warp];
    int*   c = sc[warp];

    float4 o;
    if (nnz == 0) {
        // all-masked row: softmax is uniform 1/N -> mean of h columns
        float4 s = {0,0,0,0};
        for (int r = 0; r < NN; r++) {
            float4 hv = reinterpret_cast<const float4*>(g_h + (size_t)r * DOUT)[l];
            s.x += hv.x; s.y += hv.y; s.z += hv.z; s.w += hv.w;
        }
        float inv = 1.f / (float)NN;
        o.x = leaky(s.x * inv); o.y = leaky(s.y * inv);
        o.z = leaky(s.z * inv); o.w = leaky(s.w * inv);
    } else {
        float s1i = g_s1[row];
        const int* cp = g_cols + (size_t)row * CAP;
        float m = -3.0e38f;
        for (int k = l; k < nnz; k += 32) {
            int cj = cp[k];
            float e = leaky(s1i + g_s2[cj]);
            c[k] = cj; w[k] = e;
            m = fmaxf(m, e);
        }
        __syncwarp();
#pragma unroll
        for (int off = 16; off > 0; off >>= 1)
            m = fmaxf(m, __shfl_xor_sync(FULL, m, off));
        float s = 0.f;
        for (int k = l; k < nnz; k += 32) {
            float e = expf(w[k] - m);
            w[k] = e; s += e;
        }
        __syncwarp();
#pragma unroll
        for (int off = 16; off > 0; off >>= 1)
            s += __shfl_xor_sync(FULL, s, off);
        float inv = 1.f / s;

        float4 a0 = {0,0,0,0}, a1 = {0,0,0,0};
        int k = 0;
        for (; k + 1 < nnz; k += 2) {
            float w0 = w[k], w1 = w[k+1];
            float4 v0 = reinterpret_cast<const float4*>(g_h + (size_t)c[k]   * DOUT)[l];
            float4 v1 = reinterpret_cast<const float4*>(g_h + (size_t)c[k+1] * DOUT)[l];
            a0.x += w0*v0.x; a0.y += w0*v0.y; a0.z += w0*v0.z; a0.w += w0*v0.w;
            a1.x += w1*v1.x; a1.y += w1*v1.y; a1.z += w1*v1.z; a1.w += w1*v1.w;
        }
        if (k < nnz) {
            float w0 = w[k];
            float4 v0 = reinterpret_cast<const float4*>(g_h + (size_t)c[k] * DOUT)[l];
            a0.x += w0*v0.x; a0.y += w0*v0.y; a0.z += w0*v0.z; a0.w += w0*v0.w;
        }
        o.x = leaky((a0.x + a1.x) * inv);
        o.y = leaky((a0.y + a1.y) * inv);
        o.z = leaky((a0.z + a1.z) * inv);
        o.w = leaky((a0.w + a1.w) * inv);
    }
    if (l < 16)
        *reinterpret_cast<float4*>(out + (size_t)row * 64 + l * 4) = o;
    else
        *reinterpret_cast<float4*>(out + (size_t)NN * 64 + (size_t)row * 64 + (l * 4 - 64)) = o;
}

// ---------------------------------------------------------------------------
extern "C" void kernel_launch(void* const* d_in, const int* in_sizes, int n_in,
                              void* d_out, int out_size)
{
    const float* x   = (const float*)d_in[0];
    const float* adj = (const float*)d_in[1];
    const float* W1  = (const float*)d_in[2];
    const float* b1  = (const float*)d_in[3];
    const float* W2  = (const float*)d_in[4];
    const float* b2  = (const float*)d_in[5];
    const float* Wg  = (const float*)d_in[6];
    const float* a   = (const float*)d_in[7];

    float *pA, *pB;
    cudaGetSymbolAddress((void**)&pA, g_bufA);
    cudaGetSymbolAddress((void**)&pB, g_bufB);

    build_csr<<<NN, 256>>>(adj);
    // t1 = x @ W1
    gemm_128_64<<<dim3(DH / 64, NN / 128), 128>>>(x, W1, pA, DIN, DH);
    // x1 = leaky(adj @ t1 + b1)
    spmm_leaky<<<NN / 2, 128>>>(pA, b1, pB);
    // t2 = x1 @ W2
    gemm_128_64<<<dim3(DH / 64, NN / 128), 128>>>(pB, W2, pA, DH, DH);
    // x2 = leaky(adj @ t2 + b2)
    spmm_leaky<<<NN / 2, 128>>>(pA, b2, pB);
    // h = x2 @ Wg  + fused s1/s2 scores
    gemm3_scores<<<NN / 128, 256>>>(pB, Wg, a);
    // softmax-weighted gather + output
    attn_k<<<NN / 8, 256>>>((float*)d_out);
}

// round 10
// speedup vs baseline: 1.0557x; 1.0557x over previous
#include <cuda_runtime.h>
#include <cstdint>
#include <cstddef>

#define NN   8192
#define DIN  512
#define DH   256
#define DOUT 128
#define CAP  256
#define SLOPE 0.25f
#define FULL 0xffffffffu

// ---- scratch (static device globals; no allocation allowed) ----
__device__ int   g_cols[(size_t)NN * CAP];
__device__ float g_vals[(size_t)NN * CAP];
__device__ int   g_nnz[NN];
__device__ float g_bufA[(size_t)NN * DH];
__device__ float g_bufB[(size_t)NN * DH];
__device__ float g_h[(size_t)NN * DOUT];
__device__ float g_s1[NN];
__device__ float g_s2[NN];

__device__ __forceinline__ float leaky(float x) { return x >= 0.f ? x : SLOPE * x; }

// ---------------------------------------------------------------------------
// GEMM body: BMxBN tile, BK=8, 8x8 microtile (smem/FFMA balanced),
// double-buffered, register prefetch. THREADS = BM*BN/64.
// If FUSE_SCORES (requires BN == N, single tile across N), the epilogue also
// computes s1=C_row.a[0:128], s2=C_row.a[128:256] via 16-lane shfl tree.
// ---------------------------------------------------------------------------
template<int BM, int BN, bool FUSE_SCORES>
__device__ __forceinline__ void gemm_body(
    const float* __restrict__ A, const float* __restrict__ B,
    float* __restrict__ C, int K, int N, int bx, int by, int tid,
    const float* __restrict__ avec)
{
    constexpr int THREADS = BM * BN / 64;
    constexpr int NLA = 2 * BM / THREADS;
    constexpr int NLB = 2 * BN / THREADS;
    constexpr int BN4 = BN / 4;

    __shared__ __align__(16) float As[2][8][BM + 4];
    __shared__ __align__(16) float Bs[2][8][BN + 4];

    int tx = tid % (BN / 8), ty = tid / (BN / 8);
    int m0 = by * BM, n0 = bx * BN;

    const float* Ap[NLA]; int arow[NLA], aq[NLA];
#pragma unroll
    for (int i = 0; i < NLA; i++) {
        int e = tid + i * THREADS;
        arow[i] = e >> 1; aq[i] = (e & 1) * 4;
        Ap[i] = A + (size_t)(m0 + arow[i]) * K + aq[i];
    }
    const float* Bp[NLB]; int bk[NLB], bc[NLB];
#pragma unroll
    for (int i = 0; i < NLB; i++) {
        int f = tid + i * THREADS;
        bk[i] = f / BN4; bc[i] = (f % BN4) * 4;
        Bp[i] = B + (size_t)bk[i] * N + n0 + bc[i];
    }

    float4 avs[NLA], bvs[NLB];
#pragma unroll
    for (int i = 0; i < NLA; i++) avs[i] = *reinterpret_cast<const float4*>(Ap[i]);
#pragma unroll
    for (int i = 0; i < NLB; i++) bvs[i] = *reinterpret_cast<const float4*>(Bp[i]);
#pragma unroll
    for (int i = 0; i < NLA; i++) {
        As[0][aq[i] + 0][arow[i]] = avs[i].x; As[0][aq[i] + 1][arow[i]] = avs[i].y;
        As[0][aq[i] + 2][arow[i]] = avs[i].z; As[0][aq[i] + 3][arow[i]] = avs[i].w;
    }
#pragma unroll
    for (int i = 0; i < NLB; i++)
        *reinterpret_cast<float4*>(&Bs[0][bk[i]][bc[i]]) = bvs[i];
    __syncthreads();

    float acc[8][8];
#pragma unroll
    for (int i = 0; i < 8; i++)
#pragma unroll
        for (int j = 0; j < 8; j++) acc[i][j] = 0.f;

    int ktiles = K >> 3;
    for (int tk = 0; tk < ktiles; tk++) {
        int buf = tk & 1;
        if (tk + 1 < ktiles) {
#pragma unroll
            for (int i = 0; i < NLA; i++)
                avs[i] = *reinterpret_cast<const float4*>(Ap[i] + (tk + 1) * 8);
#pragma unroll
            for (int i = 0; i < NLB; i++)
                bvs[i] = *reinterpret_cast<const float4*>(Bp[i] + (size_t)(tk + 1) * 8 * N);
        }
#pragma unroll
        for (int k = 0; k < 8; k++) {
            float4 a0 = *reinterpret_cast<const float4*>(&As[buf][k][ty * 8]);
            float4 a1 = *reinterpret_cast<const float4*>(&As[buf][k][ty * 8 + 4]);
            float4 b0 = *reinterpret_cast<const float4*>(&Bs[buf][k][tx * 8]);
            float4 b1 = *reinterpret_cast<const float4*>(&Bs[buf][k][tx * 8 + 4]);
            float ra[8] = { a0.x, a0.y, a0.z, a0.w, a1.x, a1.y, a1.z, a1.w };
            float rb[8] = { b0.x, b0.y, b0.z, b0.w, b1.x, b1.y, b1.z, b1.w };
#pragma unroll
            for (int i = 0; i < 8; i++)
#pragma unroll
                for (int j = 0; j < 8; j++) acc[i][j] += ra[i] * rb[j];
        }
        if (tk + 1 < ktiles) {
            int nb = buf ^ 1;
#pragma unroll
            for (int i = 0; i < NLA; i++) {
                As[nb][aq[i] + 0][arow[i]] = avs[i].x; As[nb][aq[i] + 1][arow[i]] = avs[i].y;
                As[nb][aq[i] + 2][arow[i]] = avs[i].z; As[nb][aq[i] + 3][arow[i]] = avs[i].w;
            }
#pragma unroll
            for (int i = 0; i < NLB; i++)
                *reinterpret_cast<float4*>(&Bs[nb][bk[i]][bc[i]]) = bvs[i];
        }
        __syncthreads();
    }

#pragma unroll
    for (int i = 0; i < 8; i++) {
        size_t off = (size_t)(m0 + ty * 8 + i) * N + n0 + tx * 8;
        float4 o0 = { acc[i][0], acc[i][1], acc[i][2], acc[i][3] };
        float4 o1 = { acc[i][4], acc[i][5], acc[i][6], acc[i][7] };
        *reinterpret_cast<float4*>(&C[off])     = o0;
        *reinterpret_cast<float4*>(&C[off + 4]) = o1;
    }

    if (FUSE_SCORES) {
        float a1v[8], a2v[8];
#pragma unroll
        for (int j = 0; j < 8; j++) {
            a1v[j] = avec[tx * 8 + j];
            a2v[j] = avec[DOUT + tx * 8 + j];
        }
#pragma unroll
        for (int i = 0; i < 8; i++) {
            float l1 = 0.f, l2 = 0.f;
#pragma unroll
            for (int j = 0; j < 8; j++) {
                l1 += acc[i][j] * a1v[j];
                l2 += acc[i][j] * a2v[j];
            }
#pragma unroll
            for (int o = 8; o > 0; o >>= 1) {
                l1 += __shfl_xor_sync(FULL, l1, o);
                l2 += __shfl_xor_sync(FULL, l2, o);
            }
            if (tx == 0) {
                int row = m0 + ty * 8 + i;
                g_s1[row] = l1;
                g_s2[row] = l2;
            }
        }
    }
}

__global__ __launch_bounds__(128) void gemm_128_64(
    const float* __restrict__ A, const float* __restrict__ B,
    float* __restrict__ C, int K, int N)
{
    gemm_body<128, 64, false>(A, B, C, K, N, blockIdx.x, blockIdx.y, threadIdx.x, nullptr);
}

// gemm3: h = x2 @ Wg (M=8192, N=128, K=256) with fused s1/s2 score epilogue.
__global__ __launch_bounds__(256) void gemm3_scores(
    const float* __restrict__ A, const float* __restrict__ B,
    const float* __restrict__ avec)
{
    gemm_body<128, 128, true>(A, B, g_h, DH, DOUT, 0, blockIdx.x, threadIdx.x, avec);
}

// ---------------------------------------------------------------------------
// Build padded CSR. One block/row, 256 thr.
// COALESCED loads: thread t owns float4 chunks {t, t+256, ..., t+1792} ->
// each warp LDG.128 covers 4 cache lines (was 32 with the block-contiguous
// layout => 8x fewer L1tex wavefronts; adj read becomes HBM-bound).
// Edge order within a row is a fixed permutation of column order; all
// consumers (softmax max/sum, weighted gathers) are order-invariant up to
// fp reassociation, so sortedness is not required.
// ---------------------------------------------------------------------------
__global__ void build_csr(const float* __restrict__ adj) {
    int row = blockIdx.x;
    int t   = threadIdx.x;
    int lane = t & 31, warp = t >> 5;
    const float4* arow = reinterpret_cast<const float4*>(adj + (size_t)row * NN);

    float4 v[8];
    int cnt = 0;
#pragma unroll
    for (int i = 0; i < 8; i++) {
        v[i] = arow[t + i * 256];
        cnt += (v[i].x > 0.f) + (v[i].y > 0.f) + (v[i].z > 0.f) + (v[i].w > 0.f);
    }

    int inc = cnt;
#pragma unroll
    for (int o = 1; o < 32; o <<= 1) {
        int u = __shfl_up_sync(FULL, inc, o);
        if (lane >= o) inc += u;
    }
    __shared__ int wsum[8], wbase[8];
    if (lane == 31) wsum[warp] = inc;
    __syncthreads();
    if (t == 0) {
        int run = 0;
#pragma unroll
        for (int w = 0; w < 8; w++) { wbase[w] = run; run += wsum[w]; }
        g_nnz[row] = run < CAP ? run : CAP;
    }
    __syncthreads();

    int pos = wbase[warp] + inc - cnt;
    int*   cr = g_cols + (size_t)row * CAP;
    float* vr = g_vals + (size_t)row * CAP;
#pragma unroll
    for (int i = 0; i < 8; i++) {
        int base = (t + i * 256) * 4;
        float vv[4] = { v[i].x, v[i].y, v[i].z, v[i].w };
#pragma unroll
        for (int j = 0; j < 4; j++) {
            if (vv[j] > 0.f) {
                if (pos < CAP) { cr[pos] = base + j; vr[pos] = vv[j]; }
                pos++;
            }
        }
    }
}

// ---------------------------------------------------------------------------
// Barrier-free SpMM + bias + leaky. 64 lanes/row (float4), 2 rows per block.
// At the L2 gather roofline (~10 TB/s effective).
// ---------------------------------------------------------------------------
__global__ __launch_bounds__(128) void spmm_leaky(
    const float* __restrict__ T, const float* __restrict__ bias,
    float* __restrict__ O)
{
    int row = blockIdx.x * 2 + (threadIdx.x >> 6);
    int l   = threadIdx.x & 63;
    int nnz = g_nnz[row];
    const int*   cp = g_cols + (size_t)row * CAP;
    const float* vp = g_vals + (size_t)row * CAP;

    float4 a0 = {0,0,0,0}, a1 = {0,0,0,0}, a2 = {0,0,0,0}, a3 = {0,0,0,0};
    int k = 0;
    for (; k + 3 < nnz; k += 4) {
        int   c0 = cp[k], c1 = cp[k+1], c2 = cp[k+2], c3 = cp[k+3];
        float w0 = vp[k], w1 = vp[k+1], w2 = vp[k+2], w3 = vp[k+3];
        float4 v0 = reinterpret_cast<const float4*>(T + (size_t)c0 * DH)[l];
        float4 v1 = reinterpret_cast<const float4*>(T + (size_t)c1 * DH)[l];
        float4 v2 = reinterpret_cast<const float4*>(T + (size_t)c2 * DH)[l];
        float4 v3 = reinterpret_cast<const float4*>(T + (size_t)c3 * DH)[l];
        a0.x += w0*v0.x; a0.y += w0*v0.y; a0.z += w0*v0.z; a0.w += w0*v0.w;
        a1.x += w1*v1.x; a1.y += w1*v1.y; a1.z += w1*v1.z; a1.w += w1*v1.w;
        a2.x += w2*v2.x; a2.y += w2*v2.y; a2.z += w2*v2.z; a2.w += w2*v2.w;
        a3.x += w3*v3.x; a3.y += w3*v3.y; a3.z += w3*v3.z; a3.w += w3*v3.w;
    }
    for (; k < nnz; k++) {
        int c0 = cp[k]; float w0 = vp[k];
        float4 v0 = reinterpret_cast<const float4*>(T + (size_t)c0 * DH)[l];
        a0.x += w0*v0.x; a0.y += w0*v0.y; a0.z += w0*v0.z; a0.w += w0*v0.w;
    }
    float4 b = reinterpret_cast<const float4*>(bias)[l];
    float4 o;
    o.x = leaky(a0.x + a1.x + a2.x + a3.x + b.x);
    o.y = leaky(a0.y + a1.y + a2.y + a3.y + b.y);
    o.z = leaky(a0.z + a1.z + a2.z + a3.z + b.z);
    o.w = leaky(a0.w + a1.w + a2.w + a3.w + b.w);
    reinterpret_cast<float4*>(O + (size_t)row * DH)[l] = o;
}

// ---------------------------------------------------------------------------
// Warp-per-row sparse attention (exact match of dense masked softmax).
// Empty-row fallback computes the column mean of h inline (prob ~6e-15/row).
// ---------------------------------------------------------------------------
__global__ __launch_bounds__(256) void attn_k(float* __restrict__ out) {
    int warp = threadIdx.x >> 5, l = threadIdx.x & 31;
    int row  = blockIdx.x * 8 + warp;
    int nnz  = g_nnz[row];

    __shared__ float sw[8][CAP];
    __shared__ int   sc[8][CAP];
    float* w = sw[warp];
    int*   c = sc[warp];

    float4 o;
    if (nnz == 0) {
        float4 s = {0,0,0,0};
        for (int r = 0; r < NN; r++) {
            float4 hv = reinterpret_cast<const float4*>(g_h + (size_t)r * DOUT)[l];
            s.x += hv.x; s.y += hv.y; s.z += hv.z; s.w += hv.w;
        }
        float inv = 1.f / (float)NN;
        o.x = leaky(s.x * inv); o.y = leaky(s.y * inv);
        o.z = leaky(s.z * inv); o.w = leaky(s.w * inv);
    } else {
        float s1i = g_s1[row];
        const int* cp = g_cols + (size_t)row * CAP;
        float m = -3.0e38f;
        for (int k = l; k < nnz; k += 32) {
            int cj = cp[k];
            float e = leaky(s1i + g_s2[cj]);
            c[k] = cj; w[k] = e;
            m = fmaxf(m, e);
        }
        __syncwarp();
#pragma unroll
        for (int off = 16; off > 0; off >>= 1)
            m = fmaxf(m, __shfl_xor_sync(FULL, m, off));
        float s = 0.f;
        for (int k = l; k < nnz; k += 32) {
            float e = expf(w[k] - m);
            w[k] = e; s += e;
        }
        __syncwarp();
#pragma unroll
        for (int off = 16; off > 0; off >>= 1)
            s += __shfl_xor_sync(FULL, s, off);
        float inv = 1.f / s;

        float4 a0 = {0,0,0,0}, a1 = {0,0,0,0};
        int k = 0;
        for (; k + 1 < nnz; k += 2) {
            float w0 = w[k], w1 = w[k+1];
            float4 v0 = reinterpret_cast<const float4*>(g_h + (size_t)c[k]   * DOUT)[l];
            float4 v1 = reinterpret_cast<const float4*>(g_h + (size_t)c[k+1] * DOUT)[l];
            a0.x += w0*v0.x; a0.y += w0*v0.y; a0.z += w0*v0.z; a0.w += w0*v0.w;
            a1.x += w1*v1.x; a1.y += w1*v1.y; a1.z += w1*v1.z; a1.w += w1*v1.w;
        }
        if (k < nnz) {
            float w0 = w[k];
            float4 v0 = reinterpret_cast<const float4*>(g_h + (size_t)c[k] * DOUT)[l];
            a0.x += w0*v0.x; a0.y += w0*v0.y; a0.z += w0*v0.z; a0.w += w0*v0.w;
        }
        o.x = leaky((a0.x + a1.x) * inv);
        o.y = leaky((a0.y + a1.y) * inv);
        o.z = leaky((a0.z + a1.z) * inv);
        o.w = leaky((a0.w + a1.w) * inv);
    }
    if (l < 16)
        *reinterpret_cast<float4*>(out + (size_t)row * 64 + l * 4) = o;
    else
        *reinterpret_cast<float4*>(out + (size_t)NN * 64 + (size_t)row * 64 + (l * 4 - 64)) = o;
}

// ---------------------------------------------------------------------------
extern "C" void kernel_launch(void* const* d_in, const int* in_sizes, int n_in,
                              void* d_out, int out_size)
{
    const float* x   = (const float*)d_in[0];
    const float* adj = (const float*)d_in[1];
    const float* W1  = (const float*)d_in[2];
    const float* b1  = (const float*)d_in[3];
    const float* W2  = (const float*)d_in[4];
    const float* b2  = (const float*)d_in[5];
    const float* Wg  = (const float*)d_in[6];
    const float* a   = (const float*)d_in[7];

    float *pA, *pB;
    cudaGetSymbolAddress((void**)&pA, g_bufA);
    cudaGetSymbolAddress((void**)&pB, g_bufB);

    build_csr<<<NN, 256>>>(adj);
    // t1 = x @ W1
    gemm_128_64<<<dim3(DH / 64, NN / 128), 128>>>(x, W1, pA, DIN, DH);
    // x1 = leaky(adj @ t1 + b1)
    spmm_leaky<<<NN / 2, 128>>>(pA, b1, pB);
    // t2 = x1 @ W2
    gemm_128_64<<<dim3(DH / 64, NN / 128), 128>>>(pB, W2, pA, DH, DH);
    // x2 = leaky(adj @ t2 + b2)
    spmm_leaky<<<NN / 2, 128>>>(pA, b2, pB);
    // h = x2 @ Wg  + fused s1/s2 scores
    gemm3_scores<<<NN / 128, 256>>>(pB, Wg, a);
    // softmax-weighted gather + output
    attn_k<<<NN / 8, 256>>>((float*)d_out);
}

// round 11
// speedup vs baseline: 1.1217x; 1.0625x over previous
#include <cuda_runtime.h>
#include <cstdint>
#include <cstddef>

#define NN   8192
#define DIN  512
#define DH   256
#define DOUT 128
#define CAP  256
#define SLOPE 0.25f
#define FULL 0xffffffffu

// ---- scratch (static device globals; no allocation allowed) ----
__device__ int   g_cols[(size_t)NN * CAP];
__device__ float g_vals[(size_t)NN * CAP];
__device__ int   g_nnz[NN];
__device__ float g_bufA[(size_t)NN * DH];
__device__ float g_bufB[(size_t)NN * DH];
__device__ float g_h[(size_t)NN * DOUT];
__device__ float g_s1p[2][NN];   // per-bx partial scores (summed in attn)
__device__ float g_s2p[2][NN];

__device__ __forceinline__ float leaky(float x) { return x >= 0.f ? x : SLOPE * x; }

// ---------------------------------------------------------------------------
// GEMM body: BMxBN tile, BK=8, 8x8 microtile, double-buffered, reg prefetch,
// and SK-way split-K WITHIN the CTA: SK warpgroups of THREADS=BM*BN/64 each
// compute the tile over K/SK, then a deterministic smem reduction combines
// partials into warpgroup 0, which stores C (and optional score partials).
// Raises resident warps x SK at unchanged per-FLOP smem cost.
// ---------------------------------------------------------------------------
template<int BM, int BN, int SK, bool FUSE_SCORES>
__device__ __forceinline__ void gemm_body(
    const float* __restrict__ A, const float* __restrict__ B,
    float* __restrict__ C, int K, int N, int bx, int by, int tid_all,
    const float* __restrict__ avec, float* __restrict__ s1out,
    float* __restrict__ s2out)
{
    constexpr int THREADS = BM * BN / 64;   // per K-slice
    constexpr int NLA = 2 * BM / THREADS;
    constexpr int NLB = 2 * BN / THREADS;
    constexpr int BN4 = BN / 4;

    __shared__ __align__(16) float As[SK][2][8][BM + 4];
    __shared__ __align__(16) float Bs[SK][2][8][BN + 4];

    int ks  = tid_all / THREADS;            // K-slice id (whole warps)
    int tid = tid_all % THREADS;
    int Khalf = K / SK;
    const float* Ab = A + ks * Khalf;               // column offset into A
    const float* Bb = B + (size_t)ks * Khalf * N;   // row offset into B

    int tx = tid % (BN / 8), ty = tid / (BN / 8);
    int m0 = by * BM, n0 = bx * BN;

    const float* Ap[NLA]; int arow[NLA], aq[NLA];
#pragma unroll
    for (int i = 0; i < NLA; i++) {
        int e = tid + i * THREADS;
        arow[i] = e >> 1; aq[i] = (e & 1) * 4;
        Ap[i] = Ab + (size_t)(m0 + arow[i]) * K + aq[i];
    }
    const float* Bp[NLB]; int bk[NLB], bc[NLB];
#pragma unroll
    for (int i = 0; i < NLB; i++) {
        int f = tid + i * THREADS;
        bk[i] = f / BN4; bc[i] = (f % BN4) * 4;
        Bp[i] = Bb + (size_t)bk[i] * N + n0 + bc[i];
    }

    float4 avs[NLA], bvs[NLB];
#pragma unroll
    for (int i = 0; i < NLA; i++) avs[i] = *reinterpret_cast<const float4*>(Ap[i]);
#pragma unroll
    for (int i = 0; i < NLB; i++) bvs[i] = *reinterpret_cast<const float4*>(Bp[i]);
#pragma unroll
    for (int i = 0; i < NLA; i++) {
        As[ks][0][aq[i] + 0][arow[i]] = avs[i].x; As[ks][0][aq[i] + 1][arow[i]] = avs[i].y;
        As[ks][0][aq[i] + 2][arow[i]] = avs[i].z; As[ks][0][aq[i] + 3][arow[i]] = avs[i].w;
    }
#pragma unroll
    for (int i = 0; i < NLB; i++)
        *reinterpret_cast<float4*>(&Bs[ks][0][bk[i]][bc[i]]) = bvs[i];
    __syncthreads();

    float acc[8][8];
#pragma unroll
    for (int i = 0; i < 8; i++)
#pragma unroll
        for (int j = 0; j < 8; j++) acc[i][j] = 0.f;

    int ktiles = Khalf >> 3;
    for (int tk = 0; tk < ktiles; tk++) {
        int buf = tk & 1;
        if (tk + 1 < ktiles) {
#pragma unroll
            for (int i = 0; i < NLA; i++)
                avs[i] = *reinterpret_cast<const float4*>(Ap[i] + (tk + 1) * 8);
#pragma unroll
            for (int i = 0; i < NLB; i++)
                bvs[i] = *reinterpret_cast<const float4*>(Bp[i] + (size_t)(tk + 1) * 8 * N);
        }
#pragma unroll
        for (int k = 0; k < 8; k++) {
            float4 a0 = *reinterpret_cast<const float4*>(&As[ks][buf][k][ty * 8]);
            float4 a1 = *reinterpret_cast<const float4*>(&As[ks][buf][k][ty * 8 + 4]);
            float4 b0 = *reinterpret_cast<const float4*>(&Bs[ks][buf][k][tx * 8]);
            float4 b1 = *reinterpret_cast<const float4*>(&Bs[ks][buf][k][tx * 8 + 4]);
            float ra[8] = { a0.x, a0.y, a0.z, a0.w, a1.x, a1.y, a1.z, a1.w };
            float rb[8] = { b0.x, b0.y, b0.z, b0.w, b1.x, b1.y, b1.z, b1.w };
#pragma unroll
            for (int i = 0; i < 8; i++)
#pragma unroll
                for (int j = 0; j < 8; j++) acc[i][j] += ra[i] * rb[j];
        }
        if (tk + 1 < ktiles) {
            int nb = buf ^ 1;
#pragma unroll
            for (int i = 0; i < NLA; i++) {
                As[ks][nb][aq[i] + 0][arow[i]] = avs[i].x; As[ks][nb][aq[i] + 1][arow[i]] = avs[i].y;
                As[ks][nb][aq[i] + 2][arow[i]] = avs[i].z; As[ks][nb][aq[i] + 3][arow[i]] = avs[i].w;
            }
#pragma unroll
            for (int i = 0; i < NLB; i++)
                *reinterpret_cast<float4*>(&Bs[ks][nb][bk[i]][bc[i]]) = bvs[i];
        }
        __syncthreads();
    }

    // split-K reduction: slices 1..SK-1 deposit partials, slice 0 accumulates
    // in fixed slice order (deterministic).
    if (SK > 1) {
        float4* red = reinterpret_cast<float4*>(&As[0][0][0][0]);
#pragma unroll
        for (int i = 0; i < 8; i++) {
            __syncthreads();
            if (ks > 0) {
                int base = ((ks - 1) * THREADS + tid) * 2;
                red[base]     = make_float4(acc[i][0], acc[i][1], acc[i][2], acc[i][3]);
                red[base + 1] = make_float4(acc[i][4], acc[i][5], acc[i][6], acc[i][7]);
            }
            __syncthreads();
            if (ks == 0) {
#pragma unroll
                for (int s = 1; s < SK; s++) {
                    int base = ((s - 1) * THREADS + tid) * 2;
                    float4 p0 = red[base], p1 = red[base + 1];
                    acc[i][0] += p0.x; acc[i][1] += p0.y; acc[i][2] += p0.z; acc[i][3] += p0.w;
                    acc[i][4] += p1.x; acc[i][5] += p1.y; acc[i][6] += p1.z; acc[i][7] += p1.w;
                }
            }
        }
    }

    if (ks == 0) {
#pragma unroll
        for (int i = 0; i < 8; i++) {
            size_t off = (size_t)(m0 + ty * 8 + i) * N + n0 + tx * 8;
            float4 o0 = { acc[i][0], acc[i][1], acc[i][2], acc[i][3] };
            float4 o1 = { acc[i][4], acc[i][5], acc[i][6], acc[i][7] };
            *reinterpret_cast<float4*>(&C[off])     = o0;
            *reinterpret_cast<float4*>(&C[off + 4]) = o1;
        }

        if (FUSE_SCORES) {
            // partial dot over this tile's BN columns; reduce across the
            // BN/8 threads sharing each row (they are adjacent warp lanes).
            constexpr int TXW = BN / 8;
            float a1v[8], a2v[8];
#pragma unroll
            for (int j = 0; j < 8; j++) {
                a1v[j] = avec[n0 + tx * 8 + j];
                a2v[j] = avec[DOUT + n0 + tx * 8 + j];
            }
#pragma unroll
            for (int i = 0; i < 8; i++) {
                float l1 = 0.f, l2 = 0.f;
#pragma unroll
                for (int j = 0; j < 8; j++) {
                    l1 += acc[i][j] * a1v[j];
                    l2 += acc[i][j] * a2v[j];
                }
#pragma unroll
                for (int o = TXW / 2; o > 0; o >>= 1) {
                    l1 += __shfl_xor_sync(FULL, l1, o);
                    l2 += __shfl_xor_sync(FULL, l2, o);
                }
                if (tx == 0) {
                    int row = m0 + ty * 8 + i;
                    s1out[row] = l1;
                    s2out[row] = l2;
                }
            }
        }
    }
}

// gemm1/gemm2: 128x64 tile, split-K=2 -> 256 thr/CTA
__global__ __launch_bounds__(256) void gemm_sk2(
    const float* __restrict__ A, const float* __restrict__ B,
    float* __restrict__ C, int K, int N)
{
    gemm_body<128, 64, 2, false>(A, B, C, K, N, blockIdx.x, blockIdx.y,
                                 threadIdx.x, nullptr, nullptr, nullptr);
}

// gemm3: h = x2 @ Wg, 64x64 tile, split-K=4 -> 256 thr/CTA, 256 CTAs,
// fused per-half score partials.
__global__ __launch_bounds__(256) void gemm3_scores(
    const float* __restrict__ A, const float* __restrict__ B,
    const float* __restrict__ avec)
{
    int bx = blockIdx.x;
    gemm_body<64, 64, 4, true>(A, B, g_h, DH, DOUT, bx, blockIdx.y,
                               threadIdx.x, avec, g_s1p[bx], g_s2p[bx]);
}

// ---------------------------------------------------------------------------
// Build padded CSR. One block/row, 256 thr, coalesced strided loads.
// Edge order is a fixed permutation of column order (consumers are
// order-invariant up to fp reassociation).
// ---------------------------------------------------------------------------
__global__ void build_csr(const float* __restrict__ adj) {
    int row = blockIdx.x;
    int t   = threadIdx.x;
    int lane = t & 31, warp = t >> 5;
    const float4* arow = reinterpret_cast<const float4*>(adj + (size_t)row * NN);

    float4 v[8];
    int cnt = 0;
#pragma unroll
    for (int i = 0; i < 8; i++) {
        v[i] = arow[t + i * 256];
        cnt += (v[i].x > 0.f) + (v[i].y > 0.f) + (v[i].z > 0.f) + (v[i].w > 0.f);
    }

    int inc = cnt;
#pragma unroll
    for (int o = 1; o < 32; o <<= 1) {
        int u = __shfl_up_sync(FULL, inc, o);
        if (lane >= o) inc += u;
    }
    __shared__ int wsum[8], wbase[8];
    if (lane == 31) wsum[warp] = inc;
    __syncthreads();
    if (t == 0) {
        int run = 0;
#pragma unroll
        for (int w = 0; w < 8; w++) { wbase[w] = run; run += wsum[w]; }
        g_nnz[row] = run < CAP ? run : CAP;
    }
    __syncthreads();

    int pos = wbase[warp] + inc - cnt;
    int*   cr = g_cols + (size_t)row * CAP;
    float* vr = g_vals + (size_t)row * CAP;
#pragma unroll
    for (int i = 0; i < 8; i++) {
        int base = (t + i * 256) * 4;
        float vv[4] = { v[i].x, v[i].y, v[i].z, v[i].w };
#pragma unroll
        for (int j = 0; j < 4; j++) {
            if (vv[j] > 0.f) {
                if (pos < CAP) { cr[pos] = base + j; vr[pos] = vv[j]; }
                pos++;
            }
        }
    }
}

// ---------------------------------------------------------------------------
// Barrier-free SpMM + bias + leaky. 64 lanes/row (float4), 2 rows per block.
// At the L2 gather roofline.
// ---------------------------------------------------------------------------
__global__ __launch_bounds__(128) void spmm_leaky(
    const float* __restrict__ T, const float* __restrict__ bias,
    float* __restrict__ O)
{
    int row = blockIdx.x * 2 + (threadIdx.x >> 6);
    int l   = threadIdx.x & 63;
    int nnz = g_nnz[row];
    const int*   cp = g_cols + (size_t)row * CAP;
    const float* vp = g_vals + (size_t)row * CAP;

    float4 a0 = {0,0,0,0}, a1 = {0,0,0,0}, a2 = {0,0,0,0}, a3 = {0,0,0,0};
    int k = 0;
    for (; k + 3 < nnz; k += 4) {
        int   c0 = cp[k], c1 = cp[k+1], c2 = cp[k+2], c3 = cp[k+3];
        float w0 = vp[k], w1 = vp[k+1], w2 = vp[k+2], w3 = vp[k+3];
        float4 v0 = reinterpret_cast<const float4*>(T + (size_t)c0 * DH)[l];
        float4 v1 = reinterpret_cast<const float4*>(T + (size_t)c1 * DH)[l];
        float4 v2 = reinterpret_cast<const float4*>(T + (size_t)c2 * DH)[l];
        float4 v3 = reinterpret_cast<const float4*>(T + (size_t)c3 * DH)[l];
        a0.x += w0*v0.x; a0.y += w0*v0.y; a0.z += w0*v0.z; a0.w += w0*v0.w;
        a1.x += w1*v1.x; a1.y += w1*v1.y; a1.z += w1*v1.z; a1.w += w1*v1.w;
        a2.x += w2*v2.x; a2.y += w2*v2.y; a2.z += w2*v2.z; a2.w += w2*v2.w;
        a3.x += w3*v3.x; a3.y += w3*v3.y; a3.z += w3*v3.z; a3.w += w3*v3.w;
    }
    for (; k < nnz; k++) {
        int c0 = cp[k]; float w0 = vp[k];
        float4 v0 = reinterpret_cast<const float4*>(T + (size_t)c0 * DH)[l];
        a0.x += w0*v0.x; a0.y += w0*v0.y; a0.z += w0*v0.z; a0.w += w0*v0.w;
    }
    float4 b = reinterpret_cast<const float4*>(bias)[l];
    float4 o;
    o.x = leaky(a0.x + a1.x + a2.x + a3.x + b.x);
    o.y = leaky(a0.y + a1.y + a2.y + a3.y + b.y);
    o.z = leaky(a0.z + a1.z + a2.z + a3.z + b.z);
    o.w = leaky(a0.w + a1.w + a2.w + a3.w + b.w);
    reinterpret_cast<float4*>(O + (size_t)row * DH)[l] = o;
}

// ---------------------------------------------------------------------------
// Warp-per-row sparse attention (exact match of dense masked softmax).
// Scores are sums of the two per-half partials (fp add is commutative;
// contributions are read, not atomically accumulated -> deterministic).
// ---------------------------------------------------------------------------
__global__ __launch_bounds__(256) void attn_k(float* __restrict__ out) {
    int warp = threadIdx.x >> 5, l = threadIdx.x & 31;
    int row  = blockIdx.x * 8 + warp;
    int nnz  = g_nnz[row];

    __shared__ float sw[8][CAP];
    __shared__ int   sc[8][CAP];
    float* w = sw[warp];
    int*   c = sc[warp];

    float4 o;
    if (nnz == 0) {
        float4 s = {0,0,0,0};
        for (int r = 0; r < NN; r++) {
            float4 hv = reinterpret_cast<const float4*>(g_h + (size_t)r * DOUT)[l];
            s.x += hv.x; s.y += hv.y; s.z += hv.z; s.w += hv.w;
        }
        float inv = 1.f / (float)NN;
        o.x = leaky(s.x * inv); o.y = leaky(s.y * inv);
        o.z = leaky(s.z * inv); o.w = leaky(s.w * inv);
    } else {
        float s1i = g_s1p[0][row] + g_s1p[1][row];
        const int* cp = g_cols + (size_t)row * CAP;
        float m = -3.0e38f;
        for (int k = l; k < nnz; k += 32) {
            int cj = cp[k];
            float e = leaky(s1i + (g_s2p[0][cj] + g_s2p[1][cj]));
            c[k] = cj; w[k] = e;
            m = fmaxf(m, e);
        }
        __syncwarp();
#pragma unroll
        for (int off = 16; off > 0; off >>= 1)
            m = fmaxf(m, __shfl_xor_sync(FULL, m, off));
        float s = 0.f;
        for (int k = l; k < nnz; k += 32) {
            float e = expf(w[k] - m);
            w[k] = e; s += e;
        }
        __syncwarp();
#pragma unroll
        for (int off = 16; off > 0; off >>= 1)
            s += __shfl_xor_sync(FULL, s, off);
        float inv = 1.f / s;

        float4 a0 = {0,0,0,0}, a1 = {0,0,0,0};
        int k = 0;
        for (; k + 1 < nnz; k += 2) {
            float w0 = w[k], w1 = w[k+1];
            float4 v0 = reinterpret_cast<const float4*>(g_h + (size_t)c[k]   * DOUT)[l];
            float4 v1 = reinterpret_cast<const float4*>(g_h + (size_t)c[k+1] * DOUT)[l];
            a0.x += w0*v0.x; a0.y += w0*v0.y; a0.z += w0*v0.z; a0.w += w0*v0.w;
            a1.x += w1*v1.x; a1.y += w1*v1.y; a1.z += w1*v1.z; a1.w += w1*v1.w;
        }
        if (k < nnz) {
            float w0 = w[k];
            float4 v0 = reinterpret_cast<const float4*>(g_h + (size_t)c[k] * DOUT)[l];
            a0.x += w0*v0.x; a0.y += w0*v0.y; a0.z += w0*v0.z; a0.w += w0*v0.w;
        }
        o.x = leaky((a0.x + a1.x) * inv);
        o.y = leaky((a0.y + a1.y) * inv);
        o.z = leaky((a0.z + a1.z) * inv);
        o.w = leaky((a0.w + a1.w) * inv);
    }
    if (l < 16)
        *reinterpret_cast<float4*>(out + (size_t)row * 64 + l * 4) = o;
    else
        *reinterpret_cast<float4*>(out + (size_t)NN * 64 + (size_t)row * 64 + (l * 4 - 64)) = o;
}

// ---------------------------------------------------------------------------
extern "C" void kernel_launch(void* const* d_in, const int* in_sizes, int n_in,
                              void* d_out, int out_size)
{
    const float* x   = (const float*)d_in[0];
    const float* adj = (const float*)d_in[1];
    const float* W1  = (const float*)d_in[2];
    const float* b1  = (const float*)d_in[3];
    const float* W2  = (const float*)d_in[4];
    const float* b2  = (const float*)d_in[5];
    const float* Wg  = (const float*)d_in[6];
    const float* a   = (const float*)d_in[7];

    float *pA, *pB;
    cudaGetSymbolAddress((void**)&pA, g_bufA);
    cudaGetSymbolAddress((void**)&pB, g_bufB);

    build_csr<<<NN, 256>>>(adj);
    // t1 = x @ W1
    gemm_sk2<<<dim3(DH / 64, NN / 128), 256>>>(x, W1, pA, DIN, DH);
    // x1 = leaky(adj @ t1 + b1)
    spmm_leaky<<<NN / 2, 128>>>(pA, b1, pB);
    // t2 = x1 @ W2
    gemm_sk2<<<dim3(DH / 64, NN / 128), 256>>>(pB, W2, pA, DH, DH);
    // x2 = leaky(adj @ t2 + b2)
    spmm_leaky<<<NN / 2, 128>>>(pA, b2, pB);
    // h = x2 @ Wg  + fused per-half s1/s2 scores (256 CTAs)
    gemm3_scores<<<dim3(2, NN / 64), 256>>>(pB, Wg, a);
    // softmax-weighted gather + output
    attn_k<<<NN / 8, 256>>>((float*)d_out);
}

// round 12
// speedup vs baseline: 1.1811x; 1.0529x over previous
#include <cuda_runtime.h>
#include <cstdint>
#include <cstddef>

#define NN   8192
#define DIN  512
#define DH   256
#define DOUT 128
#define CAP  256
#define SLOPE 0.25f
#define FULL 0xffffffffu

// ---- scratch (static device globals; no allocation allowed) ----
__device__ int   g_cols[(size_t)NN * CAP];
__device__ float g_vals[(size_t)NN * CAP];
__device__ int   g_nnz[NN];
__device__ float g_bufA[(size_t)NN * DH];
__device__ float g_bufB[(size_t)NN * DH];
__device__ float g_h[(size_t)NN * DOUT];
__device__ float g_s1p[2][NN];   // per-n-half partial scores (summed in attn)
__device__ float g_s2p[2][NN];

__device__ __forceinline__ float leaky(float x) { return x >= 0.f ? x : SLOPE * x; }

// ---------------------------------------------------------------------------
// TF32 helpers
// ---------------------------------------------------------------------------
__device__ __forceinline__ unsigned f2tf32(float x) {
    unsigned r;
    asm("cvt.rna.tf32.f32 %0, %1;" : "=r"(r) : "f"(x));
    return r;
}

__device__ __forceinline__ void mma_tf32(float* d, const unsigned* a, const unsigned* b) {
    asm volatile(
        "mma.sync.aligned.m16n8k8.row.col.f32.tf32.tf32.f32 "
        "{%0,%1,%2,%3}, {%4,%5,%6,%7}, {%8,%9}, {%0,%1,%2,%3};"
        : "+f"(d[0]), "+f"(d[1]), "+f"(d[2]), "+f"(d[3])
        : "r"(a[0]), "r"(a[1]), "r"(a[2]), "r"(a[3]), "r"(b[0]), "r"(b[1]));
}

// ---------------------------------------------------------------------------
// 3xTF32 tensor-core GEMM: C[M,N] = A[M,K] @ B[K,N], fp32-class accuracy.
// CTA tile 128x64, 256 thr = 8 warps (4m x 2n), warp tile 32x32
// (2 x 4 m16n8k8 mma tiles). BK=8, double-buffered.
// A,B staged to smem as hi/lo tf32 pairs (convert once per element);
// inner loop is pure LDS + HMMA. Smem row strides = 8 (mod 32) so all
// fragment LDS are bank-conflict-free.
// D += Ahi*Bhi + Ahi*Blo + Alo*Bhi  (error ~2^-22 per product, fp32-class).
// If SCORES: epilogue also emits s1/s2 partials over this tile's 64 columns
// into g_s1p/g_s2p[blockIdx.x] (deterministic smem reduction).
// ---------------------------------------------------------------------------
template<bool SCORES>
__global__ __launch_bounds__(256) void gemm_tf32(
    const float* __restrict__ A, const float* __restrict__ B,
    float* __restrict__ C, int K, int N, const float* __restrict__ avec)
{
    __shared__ unsigned Ah[2][8][136], Al[2][8][136];   // [buf][k][m], stride 136%32==8
    __shared__ unsigned Bh[2][8][72],  Bl[2][8][72];    // [buf][k][n], stride  72%32==8
    __shared__ float sc1[128][2], sc2[128][2];          // per-warp-col score partials

    int tid  = threadIdx.x;
    int warp = tid >> 5, lane = tid & 31;
    int g = lane >> 2, tig = lane & 3;
    int wm = (warp >> 1) * 32, wn = (warp & 1) * 32;
    int m0 = blockIdx.y * 128, n0 = blockIdx.x * 64;

    // staging: A: thread -> (row tid>>1, 4 k's); B: (row tid>>5, 2 n's)
    int arow = tid >> 1, kq = (tid & 1) * 4;
    const float* Aptr = A + (size_t)(m0 + arow) * K + kq;
    int brow = tid >> 5, bn = (tid & 31) * 2;
    const float* Bptr = B + (size_t)brow * N + n0 + bn;

    // prologue: tile 0 -> buf 0
    float4 av = *reinterpret_cast<const float4*>(Aptr);
    float2 bv = *reinterpret_cast<const float2*>(Bptr);
    {
        float ax[4] = { av.x, av.y, av.z, av.w };
#pragma unroll
        for (int j = 0; j < 4; j++) {
            unsigned h = f2tf32(ax[j]);
            Ah[0][kq + j][arow] = h;
            Al[0][kq + j][arow] = f2tf32(ax[j] - __uint_as_float(h));
        }
        float bx2[2] = { bv.x, bv.y };
#pragma unroll
        for (int j = 0; j < 2; j++) {
            unsigned h = f2tf32(bx2[j]);
            Bh[0][brow][bn + j] = h;
            Bl[0][brow][bn + j] = f2tf32(bx2[j] - __uint_as_float(h));
        }
    }
    __syncthreads();

    float d[2][4][4];
#pragma unroll
    for (int mt = 0; mt < 2; mt++)
#pragma unroll
        for (int nt = 0; nt < 4; nt++)
#pragma unroll
            for (int i = 0; i < 4; i++) d[mt][nt][i] = 0.f;

    int ktiles = K >> 3;
    for (int tk = 0; tk < ktiles; tk++) {
        int buf = tk & 1;
        if (tk + 1 < ktiles) {
            av = *reinterpret_cast<const float4*>(Aptr + (tk + 1) * 8);
            bv = *reinterpret_cast<const float2*>(Bptr + (size_t)(tk + 1) * 8 * N);
        }

        // fragments (conflict-free LDS)
        unsigned ah[2][4], al[2][4], bh[4][2], bl[4][2];
#pragma unroll
        for (int mt = 0; mt < 2; mt++) {
            int r = wm + mt * 16 + g;
            ah[mt][0] = Ah[buf][tig][r];     al[mt][0] = Al[buf][tig][r];
            ah[mt][1] = Ah[buf][tig][r + 8]; al[mt][1] = Al[buf][tig][r + 8];
            ah[mt][2] = Ah[buf][tig + 4][r];     al[mt][2] = Al[buf][tig + 4][r];
            ah[mt][3] = Ah[buf][tig + 4][r + 8]; al[mt][3] = Al[buf][tig + 4][r + 8];
        }
#pragma unroll
        for (int nt = 0; nt < 4; nt++) {
            int c = wn + nt * 8 + g;
            bh[nt][0] = Bh[buf][tig][c];     bl[nt][0] = Bl[buf][tig][c];
            bh[nt][1] = Bh[buf][tig + 4][c]; bl[nt][1] = Bl[buf][tig + 4][c];
        }
#pragma unroll
        for (int mt = 0; mt < 2; mt++)
#pragma unroll
            for (int nt = 0; nt < 4; nt++) {
                mma_tf32(d[mt][nt], ah[mt], bh[nt]);
                mma_tf32(d[mt][nt], ah[mt], bl[nt]);
                mma_tf32(d[mt][nt], al[mt], bh[nt]);
            }

        if (tk + 1 < ktiles) {
            int nb = buf ^ 1;
            float ax[4] = { av.x, av.y, av.z, av.w };
#pragma unroll
            for (int j = 0; j < 4; j++) {
                unsigned h = f2tf32(ax[j]);
                Ah[nb][kq + j][arow] = h;
                Al[nb][kq + j][arow] = f2tf32(ax[j] - __uint_as_float(h));
            }
            float bx2[2] = { bv.x, bv.y };
#pragma unroll
            for (int j = 0; j < 2; j++) {
                unsigned h = f2tf32(bx2[j]);
                Bh[nb][brow][bn + j] = h;
                Bl[nb][brow][bn + j] = f2tf32(bx2[j] - __uint_as_float(h));
            }
        }
        __syncthreads();
    }

    // write C: thread holds rows (wm+mt*16+g, +8), cols (wn+nt*8+2*tig, +1)
#pragma unroll
    for (int mt = 0; mt < 2; mt++) {
#pragma unroll
        for (int nt = 0; nt < 4; nt++) {
            int r0 = m0 + wm + mt * 16 + g;
            int cc = n0 + wn + nt * 8 + 2 * tig;
            float2 lo = { d[mt][nt][0], d[mt][nt][1] };
            float2 hi = { d[mt][nt][2], d[mt][nt][3] };
            *reinterpret_cast<float2*>(&C[(size_t)r0 * N + cc])       = lo;
            *reinterpret_cast<float2*>(&C[(size_t)(r0 + 8) * N + cc]) = hi;
        }
    }

    if (SCORES) {
        // per-thread partial over its 8 columns x 4 row-slots, reduced over
        // the 4 tig lanes (shfl), then across the 2 warp-columns via smem.
#pragma unroll
        for (int mt = 0; mt < 2; mt++) {
#pragma unroll
            for (int h = 0; h < 2; h++) {
                float l1 = 0.f, l2 = 0.f;
#pragma unroll
                for (int nt = 0; nt < 4; nt++) {
                    int cc = n0 + wn + nt * 8 + 2 * tig;
                    float c0 = d[mt][nt][2 * h], c1 = d[mt][nt][2 * h + 1];
                    l1 += c0 * avec[cc] + c1 * avec[cc + 1];
                    l2 += c0 * avec[DOUT + cc] + c1 * avec[DOUT + cc + 1];
                }
                l1 += __shfl_xor_sync(FULL, l1, 1);
                l1 += __shfl_xor_sync(FULL, l1, 2);
                l2 += __shfl_xor_sync(FULL, l2, 1);
                l2 += __shfl_xor_sync(FULL, l2, 2);
                if (tig == 0) {
                    int rl = wm + mt * 16 + g + 8 * h;   // 0..127
                    sc1[rl][warp & 1] = l1;
                    sc2[rl][warp & 1] = l2;
                }
            }
        }
        __syncthreads();
        if (tid < 128) {
            g_s1p[blockIdx.x][m0 + tid] = sc1[tid][0] + sc1[tid][1];
            g_s2p[blockIdx.x][m0 + tid] = sc2[tid][0] + sc2[tid][1];
        }
    }
}

// ---------------------------------------------------------------------------
// Build padded CSR. One block/row, 256 thr, coalesced strided loads.
// ---------------------------------------------------------------------------
__global__ void build_csr(const float* __restrict__ adj) {
    int row = blockIdx.x;
    int t   = threadIdx.x;
    int lane = t & 31, warp = t >> 5;
    const float4* arow = reinterpret_cast<const float4*>(adj + (size_t)row * NN);

    float4 v[8];
    int cnt = 0;
#pragma unroll
    for (int i = 0; i < 8; i++) {
        v[i] = arow[t + i * 256];
        cnt += (v[i].x > 0.f) + (v[i].y > 0.f) + (v[i].z > 0.f) + (v[i].w > 0.f);
    }

    int inc = cnt;
#pragma unroll
    for (int o = 1; o < 32; o <<= 1) {
        int u = __shfl_up_sync(FULL, inc, o);
        if (lane >= o) inc += u;
    }
    __shared__ int wsum[8], wbase[8];
    if (lane == 31) wsum[warp] = inc;
    __syncthreads();
    if (t == 0) {
        int run = 0;
#pragma unroll
        for (int w = 0; w < 8; w++) { wbase[w] = run; run += wsum[w]; }
        g_nnz[row] = run < CAP ? run : CAP;
    }
    __syncthreads();

    int pos = wbase[warp] + inc - cnt;
    int*   cr = g_cols + (size_t)row * CAP;
    float* vr = g_vals + (size_t)row * CAP;
#pragma unroll
    for (int i = 0; i < 8; i++) {
        int base = (t + i * 256) * 4;
        float vv[4] = { v[i].x, v[i].y, v[i].z, v[i].w };
#pragma unroll
        for (int j = 0; j < 4; j++) {
            if (vv[j] > 0.f) {
                if (pos < CAP) { cr[pos] = base + j; vr[pos] = vv[j]; }
                pos++;
            }
        }
    }
}

// ---------------------------------------------------------------------------
// Barrier-free SpMM + bias + leaky. 64 lanes/row (float4), 2 rows per block.
// ---------------------------------------------------------------------------
__global__ __launch_bounds__(128) void spmm_leaky(
    const float* __restrict__ T, const float* __restrict__ bias,
    float* __restrict__ O)
{
    int row = blockIdx.x * 2 + (threadIdx.x >> 6);
    int l   = threadIdx.x & 63;
    int nnz = g_nnz[row];
    const int*   cp = g_cols + (size_t)row * CAP;
    const float* vp = g_vals + (size_t)row * CAP;

    float4 a0 = {0,0,0,0}, a1 = {0,0,0,0}, a2 = {0,0,0,0}, a3 = {0,0,0,0};
    int k = 0;
    for (; k + 3 < nnz; k += 4) {
        int   c0 = cp[k], c1 = cp[k+1], c2 = cp[k+2], c3 = cp[k+3];
        float w0 = vp[k], w1 = vp[k+1], w2 = vp[k+2], w3 = vp[k+3];
        float4 v0 = reinterpret_cast<const float4*>(T + (size_t)c0 * DH)[l];
        float4 v1 = reinterpret_cast<const float4*>(T + (size_t)c1 * DH)[l];
        float4 v2 = reinterpret_cast<const float4*>(T + (size_t)c2 * DH)[l];
        float4 v3 = reinterpret_cast<const float4*>(T + (size_t)c3 * DH)[l];
        a0.x += w0*v0.x; a0.y += w0*v0.y; a0.z += w0*v0.z; a0.w += w0*v0.w;
        a1.x += w1*v1.x; a1.y += w1*v1.y; a1.z += w1*v1.z; a1.w += w1*v1.w;
        a2.x += w2*v2.x; a2.y += w2*v2.y; a2.z += w2*v2.z; a2.w += w2*v2.w;
        a3.x += w3*v3.x; a3.y += w3*v3.y; a3.z += w3*v3.z; a3.w += w3*v3.w;
    }
    for (; k < nnz; k++) {
        int c0 = cp[k]; float w0 = vp[k];
        float4 v0 = reinterpret_cast<const float4*>(T + (size_t)c0 * DH)[l];
        a0.x += w0*v0.x; a0.y += w0*v0.y; a0.z += w0*v0.z; a0.w += w0*v0.w;
    }
    float4 b = reinterpret_cast<const float4*>(bias)[l];
    float4 o;
    o.x = leaky(a0.x + a1.x + a2.x + a3.x + b.x);
    o.y = leaky(a0.y + a1.y + a2.y + a3.y + b.y);
    o.z = leaky(a0.z + a1.z + a2.z + a3.z + b.z);
    o.w = leaky(a0.w + a1.w + a2.w + a3.w + b.w);
    reinterpret_cast<float4*>(O + (size_t)row * DH)[l] = o;
}

// ---------------------------------------------------------------------------
// Warp-per-row sparse attention (exact match of dense masked softmax).
// Scores are sums of the two per-half partials (deterministic).
// ---------------------------------------------------------------------------
__global__ __launch_bounds__(256) void attn_k(float* __restrict__ out) {
    int warp = threadIdx.x >> 5, l = threadIdx.x & 31;
    int row  = blockIdx.x * 8 + warp;
    int nnz  = g_nnz[row];

    __shared__ float sw[8][CAP];
    __shared__ int   sc[8][CAP];
    float* w = sw[warp];
    int*   c = sc[warp];

    float4 o;
    if (nnz == 0) {
        float4 s = {0,0,0,0};
        for (int r = 0; r < NN; r++) {
            float4 hv = reinterpret_cast<const float4*>(g_h + (size_t)r * DOUT)[l];
            s.x += hv.x; s.y += hv.y; s.z += hv.z; s.w += hv.w;
        }
        float inv = 1.f / (float)NN;
        o.x = leaky(s.x * inv); o.y = leaky(s.y * inv);
        o.z = leaky(s.z * inv); o.w = leaky(s.w * inv);
    } else {
        float s1i = g_s1p[0][row] + g_s1p[1][row];
        const int* cp = g_cols + (size_t)row * CAP;
        float m = -3.0e38f;
        for (int k = l; k < nnz; k += 32) {
            int cj = cp[k];
            float e = leaky(s1i + (g_s2p[0][cj] + g_s2p[1][cj]));
            c[k] = cj; w[k] = e;
            m = fmaxf(m, e);
        }
        __syncwarp();
#pragma unroll
        for (int off = 16; off > 0; off >>= 1)
            m = fmaxf(m, __shfl_xor_sync(FULL, m, off));
        float s = 0.f;
        for (int k = l; k < nnz; k += 32) {
            float e = expf(w[k] - m);
            w[k] = e; s += e;
        }
        __syncwarp();
#pragma unroll
        for (int off = 16; off > 0; off >>= 1)
            s += __shfl_xor_sync(FULL, s, off);
        float inv = 1.f / s;

        float4 a0 = {0,0,0,0}, a1 = {0,0,0,0};
        int k = 0;
        for (; k + 1 < nnz; k += 2) {
            float w0 = w[k], w1 = w[k+1];
            float4 v0 = reinterpret_cast<const float4*>(g_h + (size_t)c[k]   * DOUT)[l];
            float4 v1 = reinterpret_cast<const float4*>(g_h + (size_t)c[k+1] * DOUT)[l];
            a0.x += w0*v0.x; a0.y += w0*v0.y; a0.z += w0*v0.z; a0.w += w0*v0.w;
            a1.x += w1*v1.x; a1.y += w1*v1.y; a1.z += w1*v1.z; a1.w += w1*v1.w;
        }
        if (k < nnz) {
            float w0 = w[k];
            float4 v0 = reinterpret_cast<const float4*>(g_h + (size_t)c[k] * DOUT)[l];
            a0.x += w0*v0.x; a0.y += w0*v0.y; a0.z += w0*v0.z; a0.w += w0*v0.w;
        }
        o.x = leaky((a0.x + a1.x) * inv);
        o.y = leaky((a0.y + a1.y) * inv);
        o.z = leaky((a0.z + a1.z) * inv);
        o.w = leaky((a0.w + a1.w) * inv);
    }
    if (l < 16)
        *reinterpret_cast<float4*>(out + (size_t)row * 64 + l * 4) = o;
    else
        *reinterpret_cast<float4*>(out + (size_t)NN * 64 + (size_t)row * 64 + (l * 4 - 64)) = o;
}

// ---------------------------------------------------------------------------
extern "C" void kernel_launch(void* const* d_in, const int* in_sizes, int n_in,
                              void* d_out, int out_size)
{
    const float* x   = (const float*)d_in[0];
    const float* adj = (const float*)d_in[1];
    const float* W1  = (const float*)d_in[2];
    const float* b1  = (const float*)d_in[3];
    const float* W2  = (const float*)d_in[4];
    const float* b2  = (const float*)d_in[5];
    const float* Wg  = (const float*)d_in[6];
    const float* a   = (const float*)d_in[7];

    float *pA, *pB, *pH;
    cudaGetSymbolAddress((void**)&pA, g_bufA);
    cudaGetSymbolAddress((void**)&pB, g_bufB);
    cudaGetSymbolAddress((void**)&pH, g_h);

    build_csr<<<NN, 256>>>(adj);
    // t1 = x @ W1
    gemm_tf32<false><<<dim3(DH / 64, NN / 128), 256>>>(x, W1, pA, DIN, DH, nullptr);
    // x1 = leaky(adj @ t1 + b1)
    spmm_leaky<<<NN / 2, 128>>>(pA, b1, pB);
    // t2 = x1 @ W2
    gemm_tf32<false><<<dim3(DH / 64, NN / 128), 256>>>(pB, W2, pA, DH, DH, nullptr);
    // x2 = leaky(adj @ t2 + b2)
    spmm_leaky<<<NN / 2, 128>>>(pA, b2, pB);
    // h = x2 @ Wg + fused per-half s1/s2 scores
    gemm_tf32<true><<<dim3(2, NN / 128), 256>>>(pB, Wg, pH, DH, DOUT, a);
    // softmax-weighted gather + output
    attn_k<<<NN / 8, 256>>>((float*)d_out);
}